// round 7
// baseline (speedup 1.0000x reference)
#include <cuda_runtime.h>
#include <cuda_bf16.h>
#include <cuda_fp16.h>
#include <cstdint>

// ============================================================================
// Problem constants
// ============================================================================
#define BDIM 4
#define TDIM 4096
#define DDIM 2048
#define MROWS (BDIM * TDIM)        // 16384 rows of x
#define EDIM  (3 * DDIM)           // 6144 output features of qkv
#define KDIM  DDIM                 // 2048 reduction dim
#define EPSF  1.1920929e-07f       // finfo(float32).eps

// GEMM tiling (mma.sync f16, single term xh*wh)
// CTA tile 128(M) x 256(N), K-chunk 64. 8 warps: 2 over M x 4 over N,
// warp tile 64x64 -> 128 B smem-read per HMMA (was 256).
#define TM 128
#define TN 256
#define TK 64                      // K-chunk (64 f16 = 128B rows, SW128)
#define NKC (KDIM / TK)            // 32 chunks
#define GEMM_THREADS 256
#define A_TILE_BYTES (TM * 128)    // 16KB
#define B_TILE_BYTES (TN * 128)    // 32KB
#define STAGE_BYTES (A_TILE_BYTES + B_TILE_BYTES)   // 48KB
#define NSTAGE 3

// ============================================================================
// Scratch (static device globals — allocation-free rule)
// ============================================================================
__device__ __half g_nhi[MROWS * DDIM];          // fp16(rmsnorm(x))
__device__ __half g_whi[EDIM * DDIM];           // fp16(W)
__device__ __half g_qkv[(size_t)MROWS * EDIM];  // fp16 qkv (201 MB)
__device__ float g_sq[MROWS * DDIM];            // sigmoid(rmsnorm(q))
__device__ float g_ww[MROWS * DDIM];            // exp(rmsnorm(k))
__device__ float g_kv[MROWS * DDIM];            // w * v
__device__ float g_pw[32 * 8192];               // chunk partials (w)
__device__ float g_pkv[32 * 8192];              // chunk partials (kv)

// ============================================================================
// Helpers
// ============================================================================
__device__ __forceinline__ uint32_t smem_u32(const void* p) {
    uint32_t a;
    asm("{ .reg .u64 t; cvta.to.shared.u64 t, %1; cvt.u32.u64 %0, t; }" : "=r"(a) : "l"(p));
    return a;
}

#define SMEM_SWIZZLE_128B(off) ((off) ^ (((off) >> 3) & 0x70))

__device__ __forceinline__ void cp_async16(uint32_t dst, const void* src) {
    asm volatile("cp.async.cg.shared.global [%0], [%1], 16;" :: "r"(dst), "l"(src));
}
__device__ __forceinline__ void cp_commit() {
    asm volatile("cp.async.commit_group;" ::: "memory");
}
__device__ __forceinline__ void cp_wait2() {
    asm volatile("cp.async.wait_group 2;" ::: "memory");
}
__device__ __forceinline__ void cp_wait1() {
    asm volatile("cp.async.wait_group 1;" ::: "memory");
}
__device__ __forceinline__ void cp_wait0() {
    asm volatile("cp.async.wait_group 0;" ::: "memory");
}

__device__ __forceinline__ void ldmx4(uint32_t* r, uint32_t addr) {
    asm volatile("ldmatrix.sync.aligned.m8n8.x4.shared.b16 {%0,%1,%2,%3}, [%4];"
                 : "=r"(r[0]), "=r"(r[1]), "=r"(r[2]), "=r"(r[3]) : "r"(addr));
}

__device__ __forceinline__ void mma16816(float* c, const uint32_t* a, const uint32_t* b) {
    asm volatile(
        "mma.sync.aligned.m16n8k16.row.col.f32.f16.f16.f32 "
        "{%0,%1,%2,%3}, {%4,%5,%6,%7}, {%8,%9}, {%0,%1,%2,%3};"
        : "+f"(c[0]), "+f"(c[1]), "+f"(c[2]), "+f"(c[3])
        : "r"(a[0]), "r"(a[1]), "r"(a[2]), "r"(a[3]), "r"(b[0]), "r"(b[1]));
}

// ============================================================================
// Block reduce (two values at once; safe for repeated calls)
// ============================================================================
__device__ __forceinline__ void blockReduce2(float& a, float& b) {
    __shared__ float sa[8], sb[8];
    int tid = threadIdx.x, wid = tid >> 5, lid = tid & 31;
    #pragma unroll
    for (int o = 16; o > 0; o >>= 1) {
        a += __shfl_xor_sync(0xffffffffu, a, o);
        b += __shfl_xor_sync(0xffffffffu, b, o);
    }
    if (lid == 0) { sa[wid] = a; sb[wid] = b; }
    __syncthreads();
    if (tid < 32) {
        a = (lid < 8) ? sa[lid] : 0.f;
        b = (lid < 8) ? sb[lid] : 0.f;
        #pragma unroll
        for (int o = 4; o > 0; o >>= 1) {
            a += __shfl_xor_sync(0xffffffffu, a, o);
            b += __shfl_xor_sync(0xffffffffu, b, o);
        }
        if (lid == 0) { sa[0] = a; sb[0] = b; }
    }
    __syncthreads();
    a = sa[0]; b = sb[0];
    __syncthreads();
}

// ============================================================================
// Kernel 0: W -> fp16
// ============================================================================
__global__ void __launch_bounds__(256) k_split_w(const float* __restrict__ w) {
    int idx = blockIdx.x * 256 + threadIdx.x;
    const int n = EDIM * DDIM;
    #pragma unroll 4
    for (int i = idx; i < n; i += gridDim.x * 256) {
        g_whi[i] = __float2half_rn(w[i]);
    }
}

// ============================================================================
// Kernel 1: rmsnorm(x) -> fp16; also copy x into out[0]
// ============================================================================
__global__ void __launch_bounds__(256) k_rms_x(const float* __restrict__ x,
                                               float* __restrict__ outx) {
    int row = blockIdx.x, tid = threadIdx.x;
    const float* xr = x + (size_t)row * DDIM;
    float v[8];
    float s = 0.f, dummy = 0.f;
    #pragma unroll
    for (int i = 0; i < 8; ++i) {
        v[i] = xr[i * 256 + tid];
        s += v[i] * v[i];
    }
    blockReduce2(s, dummy);
    float r = rsqrtf(s * (1.0f / DDIM) + EPSF);
    size_t ob = (size_t)row * DDIM;
    #pragma unroll
    for (int i = 0; i < 8; ++i) {
        int c = i * 256 + tid;
        outx[ob + c] = v[i];
        g_nhi[ob + c] = __float2half_rn(v[i] * r);
    }
}

// ============================================================================
// Kernel 2: QKV GEMM via mma.sync fp16
// C[m, e] = sum_d N[m, d] * W[e, d]   (both K-major -> D = A @ B^T)
// CTA 128x256, K-chunk 64, 3-stage cp.async, 8 warps (2M x 4N), warp 64x64.
// ============================================================================
__device__ __forceinline__ void gemm_load_chunk(uint32_t sb_stage, int m0, int n0,
                                                int kc, int tid) {
    const int k0 = kc * TK;
    const int v = tid & 7;                              // 16B vector 0..7
    const int r = tid >> 3;                             // row 0..31
    // A: 128 rows (4 per thread)
    #pragma unroll
    for (int i = 0; i < 4; ++i) {
        int row = r + i * 32;
        uint32_t dst = sb_stage +
                       SMEM_SWIZZLE_128B((uint32_t)(row * 128 + v * 16));
        cp_async16(dst, g_nhi + (size_t)(m0 + row) * KDIM + k0 + v * 8);
    }
    // B: 256 rows (8 per thread)
    #pragma unroll
    for (int i = 0; i < 8; ++i) {
        int row = r + i * 32;
        uint32_t dst = sb_stage + A_TILE_BYTES +
                       SMEM_SWIZZLE_128B((uint32_t)(row * 128 + v * 16));
        cp_async16(dst, g_whi + (size_t)(n0 + row) * KDIM + k0 + v * 8);
    }
}

__global__ void __launch_bounds__(GEMM_THREADS, 1) k_gemm() {
    extern __shared__ char smem[];
    const uint32_t sb = smem_u32(smem);
    const int tid = threadIdx.x;
    const int wid = tid >> 5, lane = tid & 31;
    const int warpM = wid & 1;          // 2 warps over M (64 each)
    const int warpN = wid >> 1;         // 4 warps over N (64 each)
    const int n0 = blockIdx.x * TN;
    const int m0 = blockIdx.y * TM;

    float c[4][8][4];
    #pragma unroll
    for (int mt = 0; mt < 4; ++mt)
        #pragma unroll
        for (int nt = 0; nt < 8; ++nt)
            #pragma unroll
            for (int j = 0; j < 4; ++j) c[mt][nt][j] = 0.f;

    gemm_load_chunk(sb + 0 * STAGE_BYTES, m0, n0, 0, tid);
    cp_commit();
    gemm_load_chunk(sb + 1 * STAGE_BYTES, m0, n0, 1, tid);
    cp_commit();

    // Precomputed per-lane smem sub-offsets
    const int aRow = warpM * 64 + (lane & 15);
    const int aKb  = (lane >> 4) << 4;
    const int bRow = warpN * 64 + (lane & 7) + ((lane & 16) >> 1);
    const int bKb  = ((lane >> 3) & 1) << 4;

    int stage = 0;
    for (int kc = 0; kc < NKC; ++kc) {
        if (kc + 2 < NKC) {
            int ls = (stage + 2); if (ls >= NSTAGE) ls -= NSTAGE;
            gemm_load_chunk(sb + ls * STAGE_BYTES, m0, n0, kc + 2, tid);
            cp_commit();
            cp_wait2();
        } else if (kc + 1 < NKC) {
            cp_wait1();
        } else {
            cp_wait0();
        }
        __syncthreads();

        const uint32_t st = sb + stage * STAGE_BYTES;
        #pragma unroll
        for (int ks = 0; ks < 4; ++ks) {
            uint32_t ah[4][4], bh[8][2];
            #pragma unroll
            for (int mt = 0; mt < 4; ++mt) {
                uint32_t off = SMEM_SWIZZLE_128B(
                    (uint32_t)((aRow + mt * 16) * 128 + ks * 32 + aKb));
                ldmx4(ah[mt], st + off);
            }
            #pragma unroll
            for (int pt = 0; pt < 4; ++pt) {
                uint32_t off = SMEM_SWIZZLE_128B(
                    (uint32_t)((bRow + pt * 16) * 128 + ks * 32 + bKb));
                uint32_t rh[4];
                ldmx4(rh, st + A_TILE_BYTES + off);
                bh[2 * pt][0] = rh[0]; bh[2 * pt][1] = rh[1];
                bh[2 * pt + 1][0] = rh[2]; bh[2 * pt + 1][1] = rh[3];
            }
            #pragma unroll
            for (int mt = 0; mt < 4; ++mt)
                #pragma unroll
                for (int nt = 0; nt < 8; ++nt)
                    mma16816(c[mt][nt], ah[mt], bh[nt]);
        }
        __syncthreads();
        if (++stage == NSTAGE) stage = 0;
    }

    // Epilogue: write fp16 qkv (half2 stores)
    const int m_base = m0 + warpM * 64;
    const int n_base = n0 + warpN * 64;
    #pragma unroll
    for (int mt = 0; mt < 4; ++mt)
        #pragma unroll
        for (int nt = 0; nt < 8; ++nt) {
            int r0 = m_base + mt * 16 + (lane >> 2);
            int cc = n_base + nt * 8 + (lane & 3) * 2;
            __half2 v0 = __floats2half2_rn(c[mt][nt][0], c[mt][nt][1]);
            __half2 v1 = __floats2half2_rn(c[mt][nt][2], c[mt][nt][3]);
            *(__half2*)(g_qkv + (size_t)r0 * EDIM + cc) = v0;
            *(__half2*)(g_qkv + (size_t)(r0 + 8) * EDIM + cc) = v1;
        }
}

// ============================================================================
// Kernel 3: rmsnorm(q), rmsnorm(k), sigmoid(q), w=exp(k), kv=w*v
// qkv is fp16; outputs fp32. half2 loads for coalescing.
// ============================================================================
__global__ void __launch_bounds__(256) k_post() {
    int row = blockIdx.x, tid = threadIdx.x;
    const __half2* q2 = (const __half2*)(g_qkv + (size_t)row * EDIM);
    float2 qv[4], kk[4], vv[4];
    float sq = 0.f, sk = 0.f;
    #pragma unroll
    for (int i = 0; i < 4; ++i) {
        int p = i * 256 + tid;                 // pair index 0..1023
        qv[i] = __half22float2(q2[p]);
        kk[i] = __half22float2(q2[p + DDIM / 2]);
        vv[i] = __half22float2(q2[p + DDIM]);
        sq += qv[i].x * qv[i].x + qv[i].y * qv[i].y;
        sk += kk[i].x * kk[i].x + kk[i].y * kk[i].y;
    }
    blockReduce2(sq, sk);
    float rq = rsqrtf(sq * (1.0f / DDIM) + EPSF);
    float rk = rsqrtf(sk * (1.0f / DDIM) + EPSF);
    size_t ob = (size_t)row * DDIM;
    #pragma unroll
    for (int i = 0; i < 4; ++i) {
        int p = i * 256 + tid;
        float2 s, w, kv;
        s.x = 1.0f / (1.0f + expf(-qv[i].x * rq));
        s.y = 1.0f / (1.0f + expf(-qv[i].y * rq));
        w.x = expf(kk[i].x * rk);
        w.y = expf(kk[i].y * rk);
        kv.x = w.x * vv[i].x;
        kv.y = w.y * vv[i].y;
        *(float2*)(g_sq + ob + 2 * p) = s;
        *(float2*)(g_ww + ob + 2 * p) = w;
        *(float2*)(g_kv + ob + 2 * p) = kv;
    }
}

// ============================================================================
// Kernel 4a/4b/4c: chunked cumsum over T per (b, d) channel, then output
// ============================================================================
__global__ void __launch_bounds__(256) k_scan_part() {
    int gid = blockIdx.x * 256 + threadIdx.x;    // 0..262143
    int d = gid & (DDIM - 1);
    int rest = gid >> 11;
    int b = rest & 3;
    int j = rest >> 2;                           // chunk 0..31
    size_t base = ((size_t)(b * TDIM + j * 128)) * DDIM + d;
    float sw = 0.f, skv = 0.f;
    #pragma unroll 4
    for (int t = 0; t < 128; ++t) {
        sw  += g_ww[base + (size_t)t * DDIM];
        skv += g_kv[base + (size_t)t * DDIM];
    }
    int ch = b * DDIM + d;
    g_pw[j * 8192 + ch] = sw;
    g_pkv[j * 8192 + ch] = skv;
}

__global__ void __launch_bounds__(256) k_scan_ex() {
    int ch = blockIdx.x * 256 + threadIdx.x;     // 0..8191
    float rw = 0.f, rkv = 0.f;
    #pragma unroll
    for (int j = 0; j < 32; ++j) {
        int i = j * 8192 + ch;
        float tw = g_pw[i];  g_pw[i]  = rw;  rw  += tw;
        float tk = g_pkv[i]; g_pkv[i] = rkv; rkv += tk;
    }
}

__global__ void __launch_bounds__(256) k_scan_apply(float* __restrict__ out2) {
    int gid = blockIdx.x * 256 + threadIdx.x;
    int d = gid & (DDIM - 1);
    int rest = gid >> 11;
    int b = rest & 3;
    int j = rest >> 2;
    size_t base = ((size_t)(b * TDIM + j * 128)) * DDIM + d;
    int ch = b * DDIM + d;
    float rw = g_pw[j * 8192 + ch];
    float rkv = g_pkv[j * 8192 + ch];
    #pragma unroll 4
    for (int t = 0; t < 128; ++t) {
        size_t i = base + (size_t)t * DDIM;
        rw  += g_ww[i];
        rkv += g_kv[i];
        float y = rkv / (rw + 1e-6f);
        out2[i] = g_sq[i] * y;
    }
}

// ============================================================================
// Launch
// ============================================================================
extern "C" void kernel_launch(void* const* d_in, const int* in_sizes, int n_in,
                              void* d_out, int out_size) {
    const float* x  = (const float*)d_in[0];   // [4, 4096, 2048]
    const float* wq = (const float*)d_in[1];   // [6144, 2048]
    float* out = (float*)d_out;                // [2, 4, 4096, 2048]

    cudaFuncSetAttribute(k_gemm, cudaFuncAttributeMaxDynamicSharedMemorySize,
                         NSTAGE * STAGE_BYTES);

    k_split_w<<<12288, 256>>>(wq);
    k_rms_x<<<MROWS, 256>>>(x, out);
    k_gemm<<<dim3(EDIM / TN, MROWS / TM), GEMM_THREADS, NSTAGE * STAGE_BYTES>>>();
    k_post<<<MROWS, 256>>>();
    k_scan_part<<<1024, 256>>>();
    k_scan_ex<<<32, 256>>>();
    k_scan_apply<<<1024, 256>>>(out + (size_t)MROWS * DDIM);
}

// round 12
// speedup vs baseline: 1.4323x; 1.4323x over previous
#include <cuda_runtime.h>
#include <cuda_bf16.h>
#include <cuda_fp16.h>
#include <cstdint>

// ============================================================================
// Problem constants
// ============================================================================
#define BDIM 4
#define TDIM 4096
#define DDIM 2048
#define MROWS (BDIM * TDIM)        // 16384 rows of x
#define EDIM  (3 * DDIM)           // 6144 output features of qkv
#define KDIM  DDIM                 // 2048 reduction dim
#define EPSF  1.1920929e-07f       // finfo(float32).eps

// GEMM tiling (mma.sync f16): CTA 128(M) x 256(N), K-chunk 64.
// 16 warps (512 thr): 4 over M x 4 over N, warp tile 32x64.
// 16 warps/SM = 4 per SMSP for latency hiding (R6 winner structure),
// N=256 CTA tile for the R7 L2-traffic win (6.4 -> 4.8 GB).
#define TM 128
#define TN 256
#define TK 64                      // K-chunk (64 f16 = 128B rows, SW128)
#define NKC (KDIM / TK)            // 32 chunks
#define GEMM_THREADS 512
#define A_TILE_BYTES (TM * 128)    // 16KB
#define B_TILE_BYTES (TN * 128)    // 32KB
#define STAGE_BYTES (A_TILE_BYTES + B_TILE_BYTES)   // 48KB
#define NSTAGE 3

// ============================================================================
// Scratch (static device globals — allocation-free rule)
// ============================================================================
__device__ __half g_nhi[MROWS * DDIM];          // fp16(rmsnorm(x))
__device__ __half g_whi[EDIM * DDIM];           // fp16(W)
__device__ __half g_qkv[(size_t)MROWS * EDIM];  // fp16 qkv (201 MB)
__device__ float g_sq[MROWS * DDIM];            // sigmoid(rmsnorm(q))
__device__ float g_ww[MROWS * DDIM];            // exp(rmsnorm(k))
__device__ float g_kv[MROWS * DDIM];            // w * v
__device__ float g_pw[32 * 8192];               // chunk partials (w)
__device__ float g_pkv[32 * 8192];              // chunk partials (kv)

// ============================================================================
// Helpers
// ============================================================================
__device__ __forceinline__ uint32_t smem_u32(const void* p) {
    uint32_t a;
    asm("{ .reg .u64 t; cvta.to.shared.u64 t, %1; cvt.u32.u64 %0, t; }" : "=r"(a) : "l"(p));
    return a;
}

#define SMEM_SWIZZLE_128B(off) ((off) ^ (((off) >> 3) & 0x70))

__device__ __forceinline__ void cp_async16(uint32_t dst, const void* src) {
    asm volatile("cp.async.cg.shared.global [%0], [%1], 16;" :: "r"(dst), "l"(src));
}
__device__ __forceinline__ void cp_commit() {
    asm volatile("cp.async.commit_group;" ::: "memory");
}
__device__ __forceinline__ void cp_wait2() {
    asm volatile("cp.async.wait_group 2;" ::: "memory");
}
__device__ __forceinline__ void cp_wait1() {
    asm volatile("cp.async.wait_group 1;" ::: "memory");
}
__device__ __forceinline__ void cp_wait0() {
    asm volatile("cp.async.wait_group 0;" ::: "memory");
}

__device__ __forceinline__ void ldmx4(uint32_t* r, uint32_t addr) {
    asm volatile("ldmatrix.sync.aligned.m8n8.x4.shared.b16 {%0,%1,%2,%3}, [%4];"
                 : "=r"(r[0]), "=r"(r[1]), "=r"(r[2]), "=r"(r[3]) : "r"(addr));
}

__device__ __forceinline__ void mma16816(float* c, const uint32_t* a, const uint32_t* b) {
    asm volatile(
        "mma.sync.aligned.m16n8k16.row.col.f32.f16.f16.f32 "
        "{%0,%1,%2,%3}, {%4,%5,%6,%7}, {%8,%9}, {%0,%1,%2,%3};"
        : "+f"(c[0]), "+f"(c[1]), "+f"(c[2]), "+f"(c[3])
        : "r"(a[0]), "r"(a[1]), "r"(a[2]), "r"(a[3]), "r"(b[0]), "r"(b[1]));
}

// ============================================================================
// Block reduce (two values at once; safe for repeated calls)
// ============================================================================
__device__ __forceinline__ void blockReduce2(float& a, float& b) {
    __shared__ float sa[8], sb[8];
    int tid = threadIdx.x, wid = tid >> 5, lid = tid & 31;
    #pragma unroll
    for (int o = 16; o > 0; o >>= 1) {
        a += __shfl_xor_sync(0xffffffffu, a, o);
        b += __shfl_xor_sync(0xffffffffu, b, o);
    }
    if (lid == 0) { sa[wid] = a; sb[wid] = b; }
    __syncthreads();
    if (tid < 32) {
        a = (lid < 8) ? sa[lid] : 0.f;
        b = (lid < 8) ? sb[lid] : 0.f;
        #pragma unroll
        for (int o = 4; o > 0; o >>= 1) {
            a += __shfl_xor_sync(0xffffffffu, a, o);
            b += __shfl_xor_sync(0xffffffffu, b, o);
        }
        if (lid == 0) { sa[0] = a; sb[0] = b; }
    }
    __syncthreads();
    a = sa[0]; b = sb[0];
    __syncthreads();
}

// ============================================================================
// Kernel 0: W -> fp16
// ============================================================================
__global__ void __launch_bounds__(256) k_split_w(const float* __restrict__ w) {
    int idx = blockIdx.x * 256 + threadIdx.x;
    const int n = EDIM * DDIM;
    #pragma unroll 4
    for (int i = idx; i < n; i += gridDim.x * 256) {
        g_whi[i] = __float2half_rn(w[i]);
    }
}

// ============================================================================
// Kernel 1: rmsnorm(x) -> fp16; also copy x into out[0]
// ============================================================================
__global__ void __launch_bounds__(256) k_rms_x(const float* __restrict__ x,
                                               float* __restrict__ outx) {
    int row = blockIdx.x, tid = threadIdx.x;
    const float* xr = x + (size_t)row * DDIM;
    float v[8];
    float s = 0.f, dummy = 0.f;
    #pragma unroll
    for (int i = 0; i < 8; ++i) {
        v[i] = xr[i * 256 + tid];
        s += v[i] * v[i];
    }
    blockReduce2(s, dummy);
    float r = rsqrtf(s * (1.0f / DDIM) + EPSF);
    size_t ob = (size_t)row * DDIM;
    #pragma unroll
    for (int i = 0; i < 8; ++i) {
        int c = i * 256 + tid;
        outx[ob + c] = v[i];
        g_nhi[ob + c] = __float2half_rn(v[i] * r);
    }
}

// ============================================================================
// Kernel 2: QKV GEMM via mma.sync fp16
// C[m, e] = sum_d N[m, d] * W[e, d]   (both K-major -> D = A @ B^T)
// CTA 128x256, K-chunk 64, 3-stage cp.async, 16 warps (4M x 4N), warp 32x64.
// ============================================================================
__device__ __forceinline__ void gemm_load_chunk(uint32_t sb_stage, int m0, int n0,
                                                int kc, int tid) {
    const int k0 = kc * TK;
    const int v = tid & 7;                              // 16B vector 0..7
    const int r = tid >> 3;                             // row 0..63
    // A: 128 rows (2 per thread)
    #pragma unroll
    for (int i = 0; i < 2; ++i) {
        int row = r + i * 64;
        uint32_t dst = sb_stage +
                       SMEM_SWIZZLE_128B((uint32_t)(row * 128 + v * 16));
        cp_async16(dst, g_nhi + (size_t)(m0 + row) * KDIM + k0 + v * 8);
    }
    // B: 256 rows (4 per thread)
    #pragma unroll
    for (int i = 0; i < 4; ++i) {
        int row = r + i * 64;
        uint32_t dst = sb_stage + A_TILE_BYTES +
                       SMEM_SWIZZLE_128B((uint32_t)(row * 128 + v * 16));
        cp_async16(dst, g_whi + (size_t)(n0 + row) * KDIM + k0 + v * 8);
    }
}

__global__ void __launch_bounds__(GEMM_THREADS, 1) k_gemm() {
    extern __shared__ char smem[];
    const uint32_t sb = smem_u32(smem);
    const int tid = threadIdx.x;
    const int wid = tid >> 5, lane = tid & 31;
    const int warpM = wid & 3;          // 4 warps over M (32 each)
    const int warpN = wid >> 2;         // 4 warps over N (64 each)
    const int n0 = blockIdx.x * TN;
    const int m0 = blockIdx.y * TM;

    float c[2][8][4];
    #pragma unroll
    for (int mt = 0; mt < 2; ++mt)
        #pragma unroll
        for (int nt = 0; nt < 8; ++nt)
            #pragma unroll
            for (int j = 0; j < 4; ++j) c[mt][nt][j] = 0.f;

    gemm_load_chunk(sb + 0 * STAGE_BYTES, m0, n0, 0, tid);
    cp_commit();
    gemm_load_chunk(sb + 1 * STAGE_BYTES, m0, n0, 1, tid);
    cp_commit();

    // Precomputed per-lane smem sub-offsets
    const int aRow = warpM * 32 + (lane & 15);
    const int aKb  = (lane >> 4) << 4;
    const int bRow = warpN * 64 + (lane & 7) + ((lane & 16) >> 1);
    const int bKb  = ((lane >> 3) & 1) << 4;

    int stage = 0;
    for (int kc = 0; kc < NKC; ++kc) {
        if (kc + 2 < NKC) {
            int ls = (stage + 2); if (ls >= NSTAGE) ls -= NSTAGE;
            gemm_load_chunk(sb + ls * STAGE_BYTES, m0, n0, kc + 2, tid);
            cp_commit();
            cp_wait2();
        } else if (kc + 1 < NKC) {
            cp_wait1();
        } else {
            cp_wait0();
        }
        __syncthreads();

        const uint32_t st = sb + stage * STAGE_BYTES;
        #pragma unroll
        for (int ks = 0; ks < 4; ++ks) {
            uint32_t ah[2][4], bh[8][2];
            #pragma unroll
            for (int mt = 0; mt < 2; ++mt) {
                uint32_t off = SMEM_SWIZZLE_128B(
                    (uint32_t)((aRow + mt * 16) * 128 + ks * 32 + aKb));
                ldmx4(ah[mt], st + off);
            }
            #pragma unroll
            for (int pt = 0; pt < 4; ++pt) {
                uint32_t off = SMEM_SWIZZLE_128B(
                    (uint32_t)((bRow + pt * 16) * 128 + ks * 32 + bKb));
                uint32_t rh[4];
                ldmx4(rh, st + A_TILE_BYTES + off);
                bh[2 * pt][0] = rh[0]; bh[2 * pt][1] = rh[1];
                bh[2 * pt + 1][0] = rh[2]; bh[2 * pt + 1][1] = rh[3];
            }
            #pragma unroll
            for (int mt = 0; mt < 2; ++mt)
                #pragma unroll
                for (int nt = 0; nt < 8; ++nt)
                    mma16816(c[mt][nt], ah[mt], bh[nt]);
        }
        __syncthreads();
        if (++stage == NSTAGE) stage = 0;
    }

    // Epilogue: write fp16 qkv (half2 stores)
    const int m_base = m0 + warpM * 32;
    const int n_base = n0 + warpN * 64;
    #pragma unroll
    for (int mt = 0; mt < 2; ++mt)
        #pragma unroll
        for (int nt = 0; nt < 8; ++nt) {
            int r0 = m_base + mt * 16 + (lane >> 2);
            int cc = n_base + nt * 8 + (lane & 3) * 2;
            __half2 v0 = __floats2half2_rn(c[mt][nt][0], c[mt][nt][1]);
            __half2 v1 = __floats2half2_rn(c[mt][nt][2], c[mt][nt][3]);
            *(__half2*)(g_qkv + (size_t)r0 * EDIM + cc) = v0;
            *(__half2*)(g_qkv + (size_t)(r0 + 8) * EDIM + cc) = v1;
        }
}

// ============================================================================
// Kernel 3: rmsnorm(q), rmsnorm(k), sigmoid(q), w=exp(k), kv=w*v
// qkv is fp16; outputs fp32. half2 loads for coalescing.
// ============================================================================
__global__ void __launch_bounds__(256) k_post() {
    int row = blockIdx.x, tid = threadIdx.x;
    const __half2* q2 = (const __half2*)(g_qkv + (size_t)row * EDIM);
    float2 qv[4], kk[4], vv[4];
    float sq = 0.f, sk = 0.f;
    #pragma unroll
    for (int i = 0; i < 4; ++i) {
        int p = i * 256 + tid;                 // pair index 0..1023
        qv[i] = __half22float2(q2[p]);
        kk[i] = __half22float2(q2[p + DDIM / 2]);
        vv[i] = __half22float2(q2[p + DDIM]);
        sq += qv[i].x * qv[i].x + qv[i].y * qv[i].y;
        sk += kk[i].x * kk[i].x + kk[i].y * kk[i].y;
    }
    blockReduce2(sq, sk);
    float rq = rsqrtf(sq * (1.0f / DDIM) + EPSF);
    float rk = rsqrtf(sk * (1.0f / DDIM) + EPSF);
    size_t ob = (size_t)row * DDIM;
    #pragma unroll
    for (int i = 0; i < 4; ++i) {
        int p = i * 256 + tid;
        float2 s, w, kv;
        s.x = 1.0f / (1.0f + expf(-qv[i].x * rq));
        s.y = 1.0f / (1.0f + expf(-qv[i].y * rq));
        w.x = expf(kk[i].x * rk);
        w.y = expf(kk[i].y * rk);
        kv.x = w.x * vv[i].x;
        kv.y = w.y * vv[i].y;
        *(float2*)(g_sq + ob + 2 * p) = s;
        *(float2*)(g_ww + ob + 2 * p) = w;
        *(float2*)(g_kv + ob + 2 * p) = kv;
    }
}

// ============================================================================
// Kernel 4a/4b/4c: chunked cumsum over T per (b, d) channel, then output
// ============================================================================
__global__ void __launch_bounds__(256) k_scan_part() {
    int gid = blockIdx.x * 256 + threadIdx.x;    // 0..262143
    int d = gid & (DDIM - 1);
    int rest = gid >> 11;
    int b = rest & 3;
    int j = rest >> 2;                           // chunk 0..31
    size_t base = ((size_t)(b * TDIM + j * 128)) * DDIM + d;
    float sw = 0.f, skv = 0.f;
    #pragma unroll 4
    for (int t = 0; t < 128; ++t) {
        sw  += g_ww[base + (size_t)t * DDIM];
        skv += g_kv[base + (size_t)t * DDIM];
    }
    int ch = b * DDIM + d;
    g_pw[j * 8192 + ch] = sw;
    g_pkv[j * 8192 + ch] = skv;
}

__global__ void __launch_bounds__(256) k_scan_ex() {
    int ch = blockIdx.x * 256 + threadIdx.x;     // 0..8191
    float rw = 0.f, rkv = 0.f;
    #pragma unroll
    for (int j = 0; j < 32; ++j) {
        int i = j * 8192 + ch;
        float tw = g_pw[i];  g_pw[i]  = rw;  rw  += tw;
        float tk = g_pkv[i]; g_pkv[i] = rkv; rkv += tk;
    }
}

__global__ void __launch_bounds__(256) k_scan_apply(float* __restrict__ out2) {
    int gid = blockIdx.x * 256 + threadIdx.x;
    int d = gid & (DDIM - 1);
    int rest = gid >> 11;
    int b = rest & 3;
    int j = rest >> 2;
    size_t base = ((size_t)(b * TDIM + j * 128)) * DDIM + d;
    int ch = b * DDIM + d;
    float rw = g_pw[j * 8192 + ch];
    float rkv = g_pkv[j * 8192 + ch];
    #pragma unroll 4
    for (int t = 0; t < 128; ++t) {
        size_t i = base + (size_t)t * DDIM;
        rw  += g_ww[i];
        rkv += g_kv[i];
        float y = rkv / (rw + 1e-6f);
        out2[i] = g_sq[i] * y;
    }
}

// ============================================================================
// Launch
// ============================================================================
extern "C" void kernel_launch(void* const* d_in, const int* in_sizes, int n_in,
                              void* d_out, int out_size) {
    const float* x  = (const float*)d_in[0];   // [4, 4096, 2048]
    const float* wq = (const float*)d_in[1];   // [6144, 2048]
    float* out = (float*)d_out;                // [2, 4, 4096, 2048]

    cudaFuncSetAttribute(k_gemm, cudaFuncAttributeMaxDynamicSharedMemorySize,
                         NSTAGE * STAGE_BYTES);

    k_split_w<<<12288, 256>>>(wq);
    k_rms_x<<<MROWS, 256>>>(x, out);
    k_gemm<<<dim3(EDIM / TN, MROWS / TM), GEMM_THREADS, NSTAGE * STAGE_BYTES>>>();
    k_post<<<MROWS, 256>>>();
    k_scan_part<<<1024, 256>>>();
    k_scan_ex<<<32, 256>>>();
    k_scan_apply<<<1024, 256>>>(out + (size_t)MROWS * DDIM);
}

// round 13
// speedup vs baseline: 1.4967x; 1.0450x over previous
#include <cuda_runtime.h>
#include <cuda_bf16.h>
#include <cuda_fp16.h>
#include <cstdint>

// ============================================================================
// Problem constants
// ============================================================================
#define BDIM 4
#define TDIM 4096
#define DDIM 2048
#define MROWS (BDIM * TDIM)        // 16384 rows of x
#define EDIM  (3 * DDIM)           // 6144 output features of qkv
#define KDIM  DDIM                 // 2048 reduction dim
#define EPSF  1.1920929e-07f       // finfo(float32).eps

// GEMM tiling (mma.sync f16): CTA 128(M) x 256(N), K-chunk 64.
// 16 warps (512 thr): 4 over M x 4 over N, warp tile 32x64.
#define TM 128
#define TN 256
#define TK 64                      // K-chunk (64 f16 = 128B rows, SW128)
#define NKC (KDIM / TK)            // 32 chunks
#define GEMM_THREADS 512
#define A_TILE_BYTES (TM * 128)    // 16KB
#define B_TILE_BYTES (TN * 128)    // 32KB
#define STAGE_BYTES (A_TILE_BYTES + B_TILE_BYTES)   // 48KB
#define NSTAGE 4

// ============================================================================
// Scratch (static device globals — allocation-free rule)
// ============================================================================
__device__ __half g_nhi[MROWS * DDIM];             // fp16(rmsnorm(x))
__device__ __half g_whi[EDIM * DDIM];              // fp16(W)
__device__ __half g_qkv[(size_t)MROWS * EDIM];     // fp16 qkv (201 MB)
__device__ __half2 g_sq[MROWS * DDIM / 2];         // fp16 sigmoid(rmsnorm(q))
__device__ __half2 g_ww[MROWS * DDIM / 2];         // fp16 exp(rmsnorm(k))
__device__ __half2 g_kv[MROWS * DDIM / 2];         // fp16 w * v
__device__ float g_pw[32 * 8192];                  // chunk partials (w, fp32)
__device__ float g_pkv[32 * 8192];                 // chunk partials (kv, fp32)

// ============================================================================
// Helpers
// ============================================================================
__device__ __forceinline__ uint32_t smem_u32(const void* p) {
    uint32_t a;
    asm("{ .reg .u64 t; cvta.to.shared.u64 t, %1; cvt.u32.u64 %0, t; }" : "=r"(a) : "l"(p));
    return a;
}

#define SMEM_SWIZZLE_128B(off) ((off) ^ (((off) >> 3) & 0x70))

__device__ __forceinline__ void cp_async16(uint32_t dst, const void* src) {
    asm volatile("cp.async.cg.shared.global [%0], [%1], 16;" :: "r"(dst), "l"(src));
}
__device__ __forceinline__ void cp_commit() {
    asm volatile("cp.async.commit_group;" ::: "memory");
}
__device__ __forceinline__ void cp_wait3() {
    asm volatile("cp.async.wait_group 3;" ::: "memory");
}
__device__ __forceinline__ void cp_wait2() {
    asm volatile("cp.async.wait_group 2;" ::: "memory");
}
__device__ __forceinline__ void cp_wait1() {
    asm volatile("cp.async.wait_group 1;" ::: "memory");
}
__device__ __forceinline__ void cp_wait0() {
    asm volatile("cp.async.wait_group 0;" ::: "memory");
}

__device__ __forceinline__ void ldmx4(uint32_t* r, uint32_t addr) {
    asm volatile("ldmatrix.sync.aligned.m8n8.x4.shared.b16 {%0,%1,%2,%3}, [%4];"
                 : "=r"(r[0]), "=r"(r[1]), "=r"(r[2]), "=r"(r[3]) : "r"(addr));
}

__device__ __forceinline__ void mma16816(float* c, const uint32_t* a, const uint32_t* b) {
    asm volatile(
        "mma.sync.aligned.m16n8k16.row.col.f32.f16.f16.f32 "
        "{%0,%1,%2,%3}, {%4,%5,%6,%7}, {%8,%9}, {%0,%1,%2,%3};"
        : "+f"(c[0]), "+f"(c[1]), "+f"(c[2]), "+f"(c[3])
        : "r"(a[0]), "r"(a[1]), "r"(a[2]), "r"(a[3]), "r"(b[0]), "r"(b[1]));
}

// ============================================================================
// Block reduce (two values at once; safe for repeated calls)
// ============================================================================
__device__ __forceinline__ void blockReduce2(float& a, float& b) {
    __shared__ float sa[8], sb[8];
    int tid = threadIdx.x, wid = tid >> 5, lid = tid & 31;
    #pragma unroll
    for (int o = 16; o > 0; o >>= 1) {
        a += __shfl_xor_sync(0xffffffffu, a, o);
        b += __shfl_xor_sync(0xffffffffu, b, o);
    }
    if (lid == 0) { sa[wid] = a; sb[wid] = b; }
    __syncthreads();
    if (tid < 32) {
        a = (lid < 8) ? sa[lid] : 0.f;
        b = (lid < 8) ? sb[lid] : 0.f;
        #pragma unroll
        for (int o = 4; o > 0; o >>= 1) {
            a += __shfl_xor_sync(0xffffffffu, a, o);
            b += __shfl_xor_sync(0xffffffffu, b, o);
        }
        if (lid == 0) { sa[0] = a; sb[0] = b; }
    }
    __syncthreads();
    a = sa[0]; b = sb[0];
    __syncthreads();
}

// ============================================================================
// Kernel 0: W -> fp16
// ============================================================================
__global__ void __launch_bounds__(256) k_split_w(const float* __restrict__ w) {
    int idx = blockIdx.x * 256 + threadIdx.x;
    const int n = EDIM * DDIM;
    #pragma unroll 4
    for (int i = idx; i < n; i += gridDim.x * 256) {
        g_whi[i] = __float2half_rn(w[i]);
    }
}

// ============================================================================
// Kernel 1: rmsnorm(x) -> fp16; also copy x into out[0]
// ============================================================================
__global__ void __launch_bounds__(256) k_rms_x(const float* __restrict__ x,
                                               float* __restrict__ outx) {
    int row = blockIdx.x, tid = threadIdx.x;
    const float* xr = x + (size_t)row * DDIM;
    float v[8];
    float s = 0.f, dummy = 0.f;
    #pragma unroll
    for (int i = 0; i < 8; ++i) {
        v[i] = xr[i * 256 + tid];
        s += v[i] * v[i];
    }
    blockReduce2(s, dummy);
    float r = rsqrtf(s * (1.0f / DDIM) + EPSF);
    size_t ob = (size_t)row * DDIM;
    #pragma unroll
    for (int i = 0; i < 8; ++i) {
        int c = i * 256 + tid;
        outx[ob + c] = v[i];
        g_nhi[ob + c] = __float2half_rn(v[i] * r);
    }
}

// ============================================================================
// Kernel 2: QKV GEMM via mma.sync fp16
// CTA 128x256, K-chunk 64, 4-stage cp.async, 16 warps (4M x 4N), warp 32x64.
// ============================================================================
__device__ __forceinline__ void gemm_load_chunk(uint32_t sb_stage, int m0, int n0,
                                                int kc, int tid) {
    const int k0 = kc * TK;
    const int v = tid & 7;                              // 16B vector 0..7
    const int r = tid >> 3;                             // row 0..63
    // A: 128 rows (2 per thread)
    #pragma unroll
    for (int i = 0; i < 2; ++i) {
        int row = r + i * 64;
        uint32_t dst = sb_stage +
                       SMEM_SWIZZLE_128B((uint32_t)(row * 128 + v * 16));
        cp_async16(dst, g_nhi + (size_t)(m0 + row) * KDIM + k0 + v * 8);
    }
    // B: 256 rows (4 per thread)
    #pragma unroll
    for (int i = 0; i < 4; ++i) {
        int row = r + i * 64;
        uint32_t dst = sb_stage + A_TILE_BYTES +
                       SMEM_SWIZZLE_128B((uint32_t)(row * 128 + v * 16));
        cp_async16(dst, g_whi + (size_t)(n0 + row) * KDIM + k0 + v * 8);
    }
}

__global__ void __launch_bounds__(GEMM_THREADS, 1) k_gemm() {
    extern __shared__ char smem[];
    const uint32_t sb = smem_u32(smem);
    const int tid = threadIdx.x;
    const int wid = tid >> 5, lane = tid & 31;
    const int warpM = wid & 3;          // 4 warps over M (32 each)
    const int warpN = wid >> 2;         // 4 warps over N (64 each)
    const int n0 = blockIdx.x * TN;
    const int m0 = blockIdx.y * TM;

    float c[2][8][4];
    #pragma unroll
    for (int mt = 0; mt < 2; ++mt)
        #pragma unroll
        for (int nt = 0; nt < 8; ++nt)
            #pragma unroll
            for (int j = 0; j < 4; ++j) c[mt][nt][j] = 0.f;

    gemm_load_chunk(sb + 0 * STAGE_BYTES, m0, n0, 0, tid);
    cp_commit();
    gemm_load_chunk(sb + 1 * STAGE_BYTES, m0, n0, 1, tid);
    cp_commit();
    gemm_load_chunk(sb + 2 * STAGE_BYTES, m0, n0, 2, tid);
    cp_commit();

    // Precomputed per-lane smem sub-offsets
    const int aRow = warpM * 32 + (lane & 15);
    const int aKb  = (lane >> 4) << 4;
    const int bRow = warpN * 64 + (lane & 7) + ((lane & 16) >> 1);
    const int bKb  = ((lane >> 3) & 1) << 4;

    int stage = 0;
    for (int kc = 0; kc < NKC; ++kc) {
        if (kc + 3 < NKC) {
            int ls = stage + 3; if (ls >= NSTAGE) ls -= NSTAGE;
            gemm_load_chunk(sb + ls * STAGE_BYTES, m0, n0, kc + 3, tid);
            cp_commit();
            cp_wait3();
        } else if (kc + 2 < NKC) {
            cp_wait2();
        } else if (kc + 1 < NKC) {
            cp_wait1();
        } else {
            cp_wait0();
        }
        __syncthreads();

        const uint32_t st = sb + stage * STAGE_BYTES;
        #pragma unroll
        for (int ks = 0; ks < 4; ++ks) {
            uint32_t ah[2][4], bh[8][2];
            #pragma unroll
            for (int mt = 0; mt < 2; ++mt) {
                uint32_t off = SMEM_SWIZZLE_128B(
                    (uint32_t)((aRow + mt * 16) * 128 + ks * 32 + aKb));
                ldmx4(ah[mt], st + off);
            }
            #pragma unroll
            for (int pt = 0; pt < 4; ++pt) {
                uint32_t off = SMEM_SWIZZLE_128B(
                    (uint32_t)((bRow + pt * 16) * 128 + ks * 32 + bKb));
                uint32_t rh[4];
                ldmx4(rh, st + A_TILE_BYTES + off);
                bh[2 * pt][0] = rh[0]; bh[2 * pt][1] = rh[1];
                bh[2 * pt + 1][0] = rh[2]; bh[2 * pt + 1][1] = rh[3];
            }
            #pragma unroll
            for (int mt = 0; mt < 2; ++mt)
                #pragma unroll
                for (int nt = 0; nt < 8; ++nt)
                    mma16816(c[mt][nt], ah[mt], bh[nt]);
        }
        __syncthreads();
        if (++stage == NSTAGE) stage = 0;
    }

    // Epilogue: write fp16 qkv (half2 stores)
    const int m_base = m0 + warpM * 32;
    const int n_base = n0 + warpN * 64;
    #pragma unroll
    for (int mt = 0; mt < 2; ++mt)
        #pragma unroll
        for (int nt = 0; nt < 8; ++nt) {
            int r0 = m_base + mt * 16 + (lane >> 2);
            int cc = n_base + nt * 8 + (lane & 3) * 2;
            __half2 v0 = __floats2half2_rn(c[mt][nt][0], c[mt][nt][1]);
            __half2 v1 = __floats2half2_rn(c[mt][nt][2], c[mt][nt][3]);
            *(__half2*)(g_qkv + (size_t)r0 * EDIM + cc) = v0;
            *(__half2*)(g_qkv + (size_t)(r0 + 8) * EDIM + cc) = v1;
        }
}

// ============================================================================
// Kernel 3: rmsnorm(q), rmsnorm(k), sigmoid(q), w=exp(k), kv=w*v
// qkv fp16 in; sq/ww/kv fp16 (half2) out. Cumsums later run in fp32.
// ============================================================================
__global__ void __launch_bounds__(256) k_post() {
    int row = blockIdx.x, tid = threadIdx.x;
    const __half2* q2 = (const __half2*)(g_qkv + (size_t)row * EDIM);
    float2 qv[4], kk[4], vv[4];
    float sq = 0.f, sk = 0.f;
    #pragma unroll
    for (int i = 0; i < 4; ++i) {
        int p = i * 256 + tid;                 // pair index 0..1023
        qv[i] = __half22float2(q2[p]);
        kk[i] = __half22float2(q2[p + DDIM / 2]);
        vv[i] = __half22float2(q2[p + DDIM]);
        sq += qv[i].x * qv[i].x + qv[i].y * qv[i].y;
        sk += kk[i].x * kk[i].x + kk[i].y * kk[i].y;
    }
    blockReduce2(sq, sk);
    float rq = rsqrtf(sq * (1.0f / DDIM) + EPSF);
    float rk = rsqrtf(sk * (1.0f / DDIM) + EPSF);
    size_t ob2 = (size_t)row * (DDIM / 2);
    #pragma unroll
    for (int i = 0; i < 4; ++i) {
        int p = i * 256 + tid;
        float sx = 1.0f / (1.0f + expf(-qv[i].x * rq));
        float sy = 1.0f / (1.0f + expf(-qv[i].y * rq));
        float wx = expf(kk[i].x * rk);
        float wy = expf(kk[i].y * rk);
        g_sq[ob2 + p] = __floats2half2_rn(sx, sy);
        g_ww[ob2 + p] = __floats2half2_rn(wx, wy);
        g_kv[ob2 + p] = __floats2half2_rn(wx * vv[i].x, wy * vv[i].y);
    }
}

// ============================================================================
// Kernel 4a/4b/4c: chunked cumsum over T per (b, d) channel, then output.
// Channel pairs: 1024 half2 lanes per (b); T split into 32 chunks of 128.
// ============================================================================
__global__ void __launch_bounds__(256) k_scan_part() {
    int gid = blockIdx.x * 256 + threadIdx.x;    // 0..131071
    int d2 = gid & 1023;                         // half2 lane
    int rest = gid >> 10;
    int b = rest & 3;
    int j = rest >> 2;                           // chunk 0..31
    size_t base = ((size_t)(b * TDIM + j * 128)) * (DDIM / 2) + d2;
    float2 sw = make_float2(0.f, 0.f), skv = make_float2(0.f, 0.f);
    #pragma unroll 4
    for (int t = 0; t < 128; ++t) {
        float2 w = __half22float2(g_ww[base + (size_t)t * (DDIM / 2)]);
        float2 kv = __half22float2(g_kv[base + (size_t)t * (DDIM / 2)]);
        sw.x += w.x;  sw.y += w.y;
        skv.x += kv.x; skv.y += kv.y;
    }
    int ch = b * DDIM + 2 * d2;
    g_pw[j * 8192 + ch] = sw.x;
    g_pw[j * 8192 + ch + 1] = sw.y;
    g_pkv[j * 8192 + ch] = skv.x;
    g_pkv[j * 8192 + ch + 1] = skv.y;
}

__global__ void __launch_bounds__(256) k_scan_ex() {
    int ch = blockIdx.x * 256 + threadIdx.x;     // 0..8191
    float rw = 0.f, rkv = 0.f;
    #pragma unroll
    for (int j = 0; j < 32; ++j) {
        int i = j * 8192 + ch;
        float tw = g_pw[i];  g_pw[i]  = rw;  rw  += tw;
        float tk = g_pkv[i]; g_pkv[i] = rkv; rkv += tk;
    }
}

__global__ void __launch_bounds__(256) k_scan_apply(float* __restrict__ out2) {
    int gid = blockIdx.x * 256 + threadIdx.x;    // 0..131071
    int d2 = gid & 1023;
    int rest = gid >> 10;
    int b = rest & 3;
    int j = rest >> 2;
    size_t base = ((size_t)(b * TDIM + j * 128)) * (DDIM / 2) + d2;
    int ch = b * DDIM + 2 * d2;
    float rw0 = g_pw[j * 8192 + ch],  rw1 = g_pw[j * 8192 + ch + 1];
    float rk0 = g_pkv[j * 8192 + ch], rk1 = g_pkv[j * 8192 + ch + 1];
    float2* o2 = (float2*)out2;
    #pragma unroll 4
    for (int t = 0; t < 128; ++t) {
        size_t i = base + (size_t)t * (DDIM / 2);
        float2 w  = __half22float2(g_ww[i]);
        float2 kv = __half22float2(g_kv[i]);
        float2 s  = __half22float2(g_sq[i]);
        rw0 += w.x;  rw1 += w.y;
        rk0 += kv.x; rk1 += kv.y;
        float y0 = rk0 / (rw0 + 1e-6f);
        float y1 = rk1 / (rw1 + 1e-6f);
        o2[i] = make_float2(s.x * y0, s.y * y1);
    }
}

// ============================================================================
// Launch
// ============================================================================
extern "C" void kernel_launch(void* const* d_in, const int* in_sizes, int n_in,
                              void* d_out, int out_size) {
    const float* x  = (const float*)d_in[0];   // [4, 4096, 2048]
    const float* wq = (const float*)d_in[1];   // [6144, 2048]
    float* out = (float*)d_out;                // [2, 4, 4096, 2048]

    cudaFuncSetAttribute(k_gemm, cudaFuncAttributeMaxDynamicSharedMemorySize,
                         NSTAGE * STAGE_BYTES);

    k_split_w<<<12288, 256>>>(wq);
    k_rms_x<<<MROWS, 256>>>(x, out);
    k_gemm<<<dim3(EDIM / TN, MROWS / TM), GEMM_THREADS, NSTAGE * STAGE_BYTES>>>();
    k_post<<<MROWS, 256>>>();
    k_scan_part<<<512, 256>>>();
    k_scan_ex<<<32, 256>>>();
    k_scan_apply<<<512, 256>>>(out + (size_t)MROWS * DDIM);
}

// round 15
// speedup vs baseline: 1.5516x; 1.0367x over previous
#include <cuda_runtime.h>
#include <cuda_bf16.h>
#include <cuda_fp16.h>
#include <cstdint>

// ============================================================================
// Problem constants
// ============================================================================
#define BDIM 4
#define TDIM 4096
#define DDIM 2048
#define MROWS (BDIM * TDIM)        // 16384 rows of x
#define EDIM  (3 * DDIM)           // 6144 output features of qkv
#define KDIM  DDIM                 // 2048 reduction dim
#define EPSF  1.1920929e-07f       // finfo(float32).eps

// GEMM tiling (mma.sync f16): CTA 128(M) x 256(N), K-chunk 64.
// 16 warps (512 thr): 4 over M x 4 over N, warp tile 32x64.
// Single __syncthreads per mainloop iteration (load-issue after the barrier).
#define TM 128
#define TN 256
#define TK 64                      // K-chunk (64 f16 = 128B rows, SW128)
#define NKC (KDIM / TK)            // 32 chunks
#define GEMM_THREADS 512
#define A_TILE_BYTES (TM * 128)    // 16KB
#define B_TILE_BYTES (TN * 128)    // 32KB
#define STAGE_BYTES (A_TILE_BYTES + B_TILE_BYTES)   // 48KB
#define NSTAGE 4

// ============================================================================
// Scratch (static device globals — allocation-free rule)
// ============================================================================
__device__ __half g_nhi[MROWS * DDIM];             // fp16(rmsnorm(x))
__device__ __half g_whi[EDIM * DDIM];              // fp16(W)
__device__ __half g_qkv[(size_t)MROWS * EDIM];     // fp16 qkv (201 MB)
__device__ __half2 g_sq[MROWS * DDIM / 2];         // fp16 sigmoid(rmsnorm(q))
__device__ __half2 g_ww[MROWS * DDIM / 2];         // fp16 exp(rmsnorm(k))
__device__ __half2 g_kv[MROWS * DDIM / 2];         // fp16 w * v
__device__ float g_pw[32 * 8192];                  // chunk partials (w, fp32)
__device__ float g_pkv[32 * 8192];                 // chunk partials (kv, fp32)

// ============================================================================
// Helpers
// ============================================================================
__device__ __forceinline__ uint32_t smem_u32(const void* p) {
    uint32_t a;
    asm("{ .reg .u64 t; cvta.to.shared.u64 t, %1; cvt.u32.u64 %0, t; }" : "=r"(a) : "l"(p));
    return a;
}

#define SMEM_SWIZZLE_128B(off) ((off) ^ (((off) >> 3) & 0x70))

__device__ __forceinline__ void cp_async16(uint32_t dst, const void* src) {
    asm volatile("cp.async.cg.shared.global [%0], [%1], 16;" :: "r"(dst), "l"(src));
}
__device__ __forceinline__ void cp_commit() {
    asm volatile("cp.async.commit_group;" ::: "memory");
}
__device__ __forceinline__ void cp_wait2() {
    asm volatile("cp.async.wait_group 2;" ::: "memory");
}
__device__ __forceinline__ void cp_wait1() {
    asm volatile("cp.async.wait_group 1;" ::: "memory");
}
__device__ __forceinline__ void cp_wait0() {
    asm volatile("cp.async.wait_group 0;" ::: "memory");
}

__device__ __forceinline__ void ldmx4(uint32_t* r, uint32_t addr) {
    asm volatile("ldmatrix.sync.aligned.m8n8.x4.shared.b16 {%0,%1,%2,%3}, [%4];"
                 : "=r"(r[0]), "=r"(r[1]), "=r"(r[2]), "=r"(r[3]) : "r"(addr));
}

__device__ __forceinline__ void mma16816(float* c, const uint32_t* a, const uint32_t* b) {
    asm volatile(
        "mma.sync.aligned.m16n8k16.row.col.f32.f16.f16.f32 "
        "{%0,%1,%2,%3}, {%4,%5,%6,%7}, {%8,%9}, {%0,%1,%2,%3};"
        : "+f"(c[0]), "+f"(c[1]), "+f"(c[2]), "+f"(c[3])
        : "r"(a[0]), "r"(a[1]), "r"(a[2]), "r"(a[3]), "r"(b[0]), "r"(b[1]));
}

// ============================================================================
// Block reduce (two values at once; safe for repeated calls)
// ============================================================================
__device__ __forceinline__ void blockReduce2(float& a, float& b) {
    __shared__ float sa[8], sb[8];
    int tid = threadIdx.x, wid = tid >> 5, lid = tid & 31;
    #pragma unroll
    for (int o = 16; o > 0; o >>= 1) {
        a += __shfl_xor_sync(0xffffffffu, a, o);
        b += __shfl_xor_sync(0xffffffffu, b, o);
    }
    if (lid == 0) { sa[wid] = a; sb[wid] = b; }
    __syncthreads();
    if (tid < 32) {
        a = (lid < 8) ? sa[lid] : 0.f;
        b = (lid < 8) ? sb[lid] : 0.f;
        #pragma unroll
        for (int o = 4; o > 0; o >>= 1) {
            a += __shfl_xor_sync(0xffffffffu, a, o);
            b += __shfl_xor_sync(0xffffffffu, b, o);
        }
        if (lid == 0) { sa[0] = a; sb[0] = b; }
    }
    __syncthreads();
    a = sa[0]; b = sb[0];
    __syncthreads();
}

// ============================================================================
// Kernel 0: W -> fp16
// ============================================================================
__global__ void __launch_bounds__(256) k_split_w(const float* __restrict__ w) {
    int idx = blockIdx.x * 256 + threadIdx.x;
    const int n = EDIM * DDIM;
    #pragma unroll 4
    for (int i = idx; i < n; i += gridDim.x * 256) {
        g_whi[i] = __float2half_rn(w[i]);
    }
}

// ============================================================================
// Kernel 1: rmsnorm(x) -> fp16; also copy x into out[0]
// ============================================================================
__global__ void __launch_bounds__(256) k_rms_x(const float* __restrict__ x,
                                               float* __restrict__ outx) {
    int row = blockIdx.x, tid = threadIdx.x;
    const float* xr = x + (size_t)row * DDIM;
    float v[8];
    float s = 0.f, dummy = 0.f;
    #pragma unroll
    for (int i = 0; i < 8; ++i) {
        v[i] = xr[i * 256 + tid];
        s += v[i] * v[i];
    }
    blockReduce2(s, dummy);
    float r = rsqrtf(s * (1.0f / DDIM) + EPSF);
    size_t ob = (size_t)row * DDIM;
    #pragma unroll
    for (int i = 0; i < 8; ++i) {
        int c = i * 256 + tid;
        outx[ob + c] = v[i];
        g_nhi[ob + c] = __float2half_rn(v[i] * r);
    }
}

// ============================================================================
// Kernel 2: QKV GEMM via mma.sync fp16
// CTA 128x256, K-chunk 64, 4-stage cp.async, 16 warps (4M x 4N), warp 32x64.
// ONE __syncthreads per mainloop iteration: the top barrier orders
// (a) cp.async data visibility after the per-thread wait, and
// (b) all warps' reads of stage (kc-1)%4 before its overwrite (the chunk
//     kc+3 load targets (kc+3)%4 == (kc-1)%4 and is issued only after it).
// ============================================================================
__device__ __forceinline__ void gemm_load_chunk(uint32_t sb_stage, int m0, int n0,
                                                int kc, int tid) {
    const int k0 = kc * TK;
    const int v = tid & 7;                              // 16B vector 0..7
    const int r = tid >> 3;                             // row 0..63
    // A: 128 rows (2 per thread)
    #pragma unroll
    for (int i = 0; i < 2; ++i) {
        int row = r + i * 64;
        uint32_t dst = sb_stage +
                       SMEM_SWIZZLE_128B((uint32_t)(row * 128 + v * 16));
        cp_async16(dst, g_nhi + (size_t)(m0 + row) * KDIM + k0 + v * 8);
    }
    // B: 256 rows (4 per thread)
    #pragma unroll
    for (int i = 0; i < 4; ++i) {
        int row = r + i * 64;
        uint32_t dst = sb_stage + A_TILE_BYTES +
                       SMEM_SWIZZLE_128B((uint32_t)(row * 128 + v * 16));
        cp_async16(dst, g_whi + (size_t)(n0 + row) * KDIM + k0 + v * 8);
    }
}

__global__ void __launch_bounds__(GEMM_THREADS, 1) k_gemm() {
    extern __shared__ char smem[];
    const uint32_t sb = smem_u32(smem);
    const int tid = threadIdx.x;
    const int wid = tid >> 5, lane = tid & 31;
    const int warpM = wid & 3;          // 4 warps over M (32 each)
    const int warpN = wid >> 2;         // 4 warps over N (64 each)
    const int n0 = blockIdx.x * TN;
    const int m0 = blockIdx.y * TM;

    float c[2][8][4];
    #pragma unroll
    for (int mt = 0; mt < 2; ++mt)
        #pragma unroll
        for (int nt = 0; nt < 8; ++nt)
            #pragma unroll
            for (int j = 0; j < 4; ++j) c[mt][nt][j] = 0.f;

    gemm_load_chunk(sb + 0 * STAGE_BYTES, m0, n0, 0, tid);
    cp_commit();
    gemm_load_chunk(sb + 1 * STAGE_BYTES, m0, n0, 1, tid);
    cp_commit();
    gemm_load_chunk(sb + 2 * STAGE_BYTES, m0, n0, 2, tid);
    cp_commit();

    // Precomputed per-lane smem sub-offsets
    const int aRow = warpM * 32 + (lane & 15);
    const int aKb  = (lane >> 4) << 4;
    const int bRow = warpN * 64 + (lane & 7) + ((lane & 16) >> 1);
    const int bKb  = ((lane >> 3) & 1) << 4;

    int stage = 0;
    for (int kc = 0; kc < NKC; ++kc) {
        // Retire chunk kc (per-thread), then one full-block barrier.
        if (kc + 3 < NKC)      cp_wait2();
        else if (kc + 2 < NKC) cp_wait2();
        else if (kc + 1 < NKC) cp_wait1();
        else                   cp_wait0();
        __syncthreads();

        // Safe to overwrite stage (kc+3)%4 == (kc-1)%4 now.
        if (kc + 3 < NKC) {
            int ls = stage + 3; if (ls >= NSTAGE) ls -= NSTAGE;
            gemm_load_chunk(sb + ls * STAGE_BYTES, m0, n0, kc + 3, tid);
            cp_commit();
        }

        const uint32_t st = sb + stage * STAGE_BYTES;
        #pragma unroll
        for (int ks = 0; ks < 4; ++ks) {
            uint32_t ah[2][4], bh[8][2];
            #pragma unroll
            for (int mt = 0; mt < 2; ++mt) {
                uint32_t off = SMEM_SWIZZLE_128B(
                    (uint32_t)((aRow + mt * 16) * 128 + ks * 32 + aKb));
                ldmx4(ah[mt], st + off);
            }
            #pragma unroll
            for (int pt = 0; pt < 4; ++pt) {
                uint32_t off = SMEM_SWIZZLE_128B(
                    (uint32_t)((bRow + pt * 16) * 128 + ks * 32 + bKb));
                uint32_t rh[4];
                ldmx4(rh, st + A_TILE_BYTES + off);
                bh[2 * pt][0] = rh[0]; bh[2 * pt][1] = rh[1];
                bh[2 * pt + 1][0] = rh[2]; bh[2 * pt + 1][1] = rh[3];
            }
            #pragma unroll
            for (int mt = 0; mt < 2; ++mt)
                #pragma unroll
                for (int nt = 0; nt < 8; ++nt)
                    mma16816(c[mt][nt], ah[mt], bh[nt]);
        }
        if (++stage == NSTAGE) stage = 0;
    }

    // Epilogue: write fp16 qkv (half2 stores)
    const int m_base = m0 + warpM * 32;
    const int n_base = n0 + warpN * 64;
    #pragma unroll
    for (int mt = 0; mt < 2; ++mt)
        #pragma unroll
        for (int nt = 0; nt < 8; ++nt) {
            int r0 = m_base + mt * 16 + (lane >> 2);
            int cc = n_base + nt * 8 + (lane & 3) * 2;
            __half2 v0 = __floats2half2_rn(c[mt][nt][0], c[mt][nt][1]);
            __half2 v1 = __floats2half2_rn(c[mt][nt][2], c[mt][nt][3]);
            *(__half2*)(g_qkv + (size_t)r0 * EDIM + cc) = v0;
            *(__half2*)(g_qkv + (size_t)(r0 + 8) * EDIM + cc) = v1;
        }
}

// ============================================================================
// Kernel 3: rmsnorm(q), rmsnorm(k), sigmoid(q), w=exp(k), kv=w*v
// qkv fp16 in; sq/ww/kv fp16 (half2) out. Cumsums later run in fp32.
// ============================================================================
__global__ void __launch_bounds__(256) k_post() {
    int row = blockIdx.x, tid = threadIdx.x;
    const __half2* q2 = (const __half2*)(g_qkv + (size_t)row * EDIM);
    float2 qv[4], kk[4], vv[4];
    float sq = 0.f, sk = 0.f;
    #pragma unroll
    for (int i = 0; i < 4; ++i) {
        int p = i * 256 + tid;                 // pair index 0..1023
        qv[i] = __half22float2(q2[p]);
        kk[i] = __half22float2(q2[p + DDIM / 2]);
        vv[i] = __half22float2(q2[p + DDIM]);
        sq += qv[i].x * qv[i].x + qv[i].y * qv[i].y;
        sk += kk[i].x * kk[i].x + kk[i].y * kk[i].y;
    }
    blockReduce2(sq, sk);
    float rq = rsqrtf(sq * (1.0f / DDIM) + EPSF);
    float rk = rsqrtf(sk * (1.0f / DDIM) + EPSF);
    size_t ob2 = (size_t)row * (DDIM / 2);
    #pragma unroll
    for (int i = 0; i < 4; ++i) {
        int p = i * 256 + tid;
        float sx = 1.0f / (1.0f + expf(-qv[i].x * rq));
        float sy = 1.0f / (1.0f + expf(-qv[i].y * rq));
        float wx = expf(kk[i].x * rk);
        float wy = expf(kk[i].y * rk);
        g_sq[ob2 + p] = __floats2half2_rn(sx, sy);
        g_ww[ob2 + p] = __floats2half2_rn(wx, wy);
        g_kv[ob2 + p] = __floats2half2_rn(wx * vv[i].x, wy * vv[i].y);
    }
}

// ============================================================================
// Kernel 4a/4b/4c: chunked cumsum over T per (b, d) channel, then output.
// ============================================================================
__global__ void __launch_bounds__(256) k_scan_part() {
    int gid = blockIdx.x * 256 + threadIdx.x;    // 0..131071
    int d2 = gid & 1023;                         // half2 lane
    int rest = gid >> 10;
    int b = rest & 3;
    int j = rest >> 2;                           // chunk 0..31
    size_t base = ((size_t)(b * TDIM + j * 128)) * (DDIM / 2) + d2;
    float2 sw = make_float2(0.f, 0.f), skv = make_float2(0.f, 0.f);
    #pragma unroll 4
    for (int t = 0; t < 128; ++t) {
        float2 w = __half22float2(g_ww[base + (size_t)t * (DDIM / 2)]);
        float2 kv = __half22float2(g_kv[base + (size_t)t * (DDIM / 2)]);
        sw.x += w.x;  sw.y += w.y;
        skv.x += kv.x; skv.y += kv.y;
    }
    int ch = b * DDIM + 2 * d2;
    g_pw[j * 8192 + ch] = sw.x;
    g_pw[j * 8192 + ch + 1] = sw.y;
    g_pkv[j * 8192 + ch] = skv.x;
    g_pkv[j * 8192 + ch + 1] = skv.y;
}

__global__ void __launch_bounds__(256) k_scan_ex() {
    int ch = blockIdx.x * 256 + threadIdx.x;     // 0..8191
    float rw = 0.f, rkv = 0.f;
    #pragma unroll
    for (int j = 0; j < 32; ++j) {
        int i = j * 8192 + ch;
        float tw = g_pw[i];  g_pw[i]  = rw;  rw  += tw;
        float tk = g_pkv[i]; g_pkv[i] = rkv; rkv += tk;
    }
}

__global__ void __launch_bounds__(256) k_scan_apply(float* __restrict__ out2) {
    int gid = blockIdx.x * 256 + threadIdx.x;    // 0..131071
    int d2 = gid & 1023;
    int rest = gid >> 10;
    int b = rest & 3;
    int j = rest >> 2;
    size_t base = ((size_t)(b * TDIM + j * 128)) * (DDIM / 2) + d2;
    int ch = b * DDIM + 2 * d2;
    float rw0 = g_pw[j * 8192 + ch],  rw1 = g_pw[j * 8192 + ch + 1];
    float rk0 = g_pkv[j * 8192 + ch], rk1 = g_pkv[j * 8192 + ch + 1];
    float2* o2 = (float2*)out2;
    #pragma unroll 4
    for (int t = 0; t < 128; ++t) {
        size_t i = base + (size_t)t * (DDIM / 2);
        float2 w  = __half22float2(g_ww[i]);
        float2 kv = __half22float2(g_kv[i]);
        float2 s  = __half22float2(g_sq[i]);
        rw0 += w.x;  rw1 += w.y;
        rk0 += kv.x; rk1 += kv.y;
        float y0 = rk0 / (rw0 + 1e-6f);
        float y1 = rk1 / (rw1 + 1e-6f);
        o2[i] = make_float2(s.x * y0, s.y * y1);
    }
}

// ============================================================================
// Launch
// ============================================================================
extern "C" void kernel_launch(void* const* d_in, const int* in_sizes, int n_in,
                              void* d_out, int out_size) {
    const float* x  = (const float*)d_in[0];   // [4, 4096, 2048]
    const float* wq = (const float*)d_in[1];   // [6144, 2048]
    float* out = (float*)d_out;                // [2, 4, 4096, 2048]

    cudaFuncSetAttribute(k_gemm, cudaFuncAttributeMaxDynamicSharedMemorySize,
                         NSTAGE * STAGE_BYTES);

    k_split_w<<<12288, 256>>>(wq);
    k_rms_x<<<MROWS, 256>>>(x, out);
    k_gemm<<<dim3(EDIM / TN, MROWS / TM), GEMM_THREADS, NSTAGE * STAGE_BYTES>>>();
    k_post<<<MROWS, 256>>>();
    k_scan_part<<<512, 256>>>();
    k_scan_ex<<<32, 256>>>();
    k_scan_apply<<<512, 256>>>(out + (size_t)MROWS * DDIM);
}